// round 1
// baseline (speedup 1.0000x reference)
#include <cuda_runtime.h>
#include <math.h>

#define BATCH 2
#define NSEQ 1536
#define DIMX 1536
#define HEADS 8
#define DK 64
#define HD 512          // HEADS*DK
#define BN 3072         // BATCH*NSEQ
#define NPOS 3071       // 2N-1
#define NRPFK 192

// ---------------- scratch (static device arrays; no allocation) ----------------
__device__ __align__(16) float g_qc[16 * 1536 * 64];   // q*scale + rel_content_bias, [b*h][i][d]
__device__ __align__(16) float g_qr[16 * 1536 * 64];   // q*scale + rel_pos_bias
__device__ __align__(16) float g_k [16 * 1536 * 64];
__device__ __align__(16) float g_v [16 * 1536 * 64];
__device__ __align__(16) float g_relk[3071 * 512];     // pos_embed @ Wrel, [j2][h*64+d]
__device__ __align__(16) float g_ao[3072 * 512];       // attention out, [b*n][h*64+d]

// ---------------- fused QKV projection GEMM (128x128 tile, 8x8/thread) ----------------
__global__ __launch_bounds__(256) void qkv_gemm(
    const float* __restrict__ x, const float* __restrict__ Wq,
    const float* __restrict__ Wk, const float* __restrict__ Wv,
    const float* __restrict__ rcb, const float* __restrict__ rpb)
{
    const int z = blockIdx.z;                       // 0=q, 1=k, 2=v
    const float* Bm = (z == 0) ? Wq : (z == 1) ? Wk : Wv;
    const int m0 = blockIdx.y * 128;
    const int n0 = blockIdx.x * 128;

    __shared__ float As[8][128];
    __shared__ float Bs[8][128];

    const int tid  = threadIdx.x;
    const int arow = tid >> 1, akq = (tid & 1) * 4;
    const int bkk  = tid >> 5, bcol = (tid & 31) * 4;
    const int tr   = tid >> 4, tc = tid & 15;

    float acc[8][8];
    #pragma unroll
    for (int i = 0; i < 8; i++)
        #pragma unroll
        for (int j = 0; j < 8; j++) acc[i][j] = 0.f;

    for (int k0 = 0; k0 < DIMX; k0 += 8) {
        float4 av = *(const float4*)&x [(m0 + arow) * DIMX + k0 + akq];
        float4 bv = *(const float4*)&Bm[(k0 + bkk) * HD + n0 + bcol];
        __syncthreads();
        As[akq + 0][arow] = av.x; As[akq + 1][arow] = av.y;
        As[akq + 2][arow] = av.z; As[akq + 3][arow] = av.w;
        *(float4*)&Bs[bkk][bcol] = bv;
        __syncthreads();
        #pragma unroll
        for (int kk = 0; kk < 8; kk++) {
            float4 a0 = *(const float4*)&As[kk][tr * 8];
            float4 a1 = *(const float4*)&As[kk][tr * 8 + 4];
            float4 b0 = *(const float4*)&Bs[kk][tc * 8];
            float4 b1 = *(const float4*)&Bs[kk][tc * 8 + 4];
            float a[8] = {a0.x, a0.y, a0.z, a0.w, a1.x, a1.y, a1.z, a1.w};
            float b[8] = {b0.x, b0.y, b0.z, b0.w, b1.x, b1.y, b1.z, b1.w};
            #pragma unroll
            for (int i = 0; i < 8; i++)
                #pragma unroll
                for (int j = 0; j < 8; j++) acc[i][j] += a[i] * b[j];
        }
    }

    // epilogue: relayout to [b*H+h][i][d]; q gets scale + biases (two outputs)
    #pragma unroll
    for (int i = 0; i < 8; i++) {
        int gm = m0 + tr * 8 + i;
        int bb = gm / NSEQ;
        int ii = gm - bb * NSEQ;
        #pragma unroll
        for (int j = 0; j < 8; j++) {
            int gn = n0 + tc * 8 + j;
            int hh = gn >> 6, dd = gn & 63;
            int idx = ((bb * HEADS + hh) * NSEQ + ii) * DK + dd;
            float v = acc[i][j];
            if (z == 0) {
                g_qc[idx] = v * 0.125f + rcb[gn];
                g_qr[idx] = v * 0.125f + rpb[gn];
            } else if (z == 1) {
                g_k[idx] = v;
            } else {
                g_v[idx] = v;
            }
        }
    }
}

// ---------------- generic SGEMM with optional bias (row guards on M) ----------------
__global__ __launch_bounds__(256) void sgemm_bias(
    const float* __restrict__ A, const float* __restrict__ Bm, float* __restrict__ C,
    int M, int N, int K, const float* __restrict__ bias)
{
    const int m0 = blockIdx.y * 128;
    const int n0 = blockIdx.x * 128;

    __shared__ float As[8][128];
    __shared__ float Bs[8][128];

    const int tid  = threadIdx.x;
    const int arow = tid >> 1, akq = (tid & 1) * 4;
    const int bkk  = tid >> 5, bcol = (tid & 31) * 4;
    const int tr   = tid >> 4, tc = tid & 15;

    float acc[8][8];
    #pragma unroll
    for (int i = 0; i < 8; i++)
        #pragma unroll
        for (int j = 0; j < 8; j++) acc[i][j] = 0.f;

    for (int k0 = 0; k0 < K; k0 += 8) {
        float4 av = make_float4(0.f, 0.f, 0.f, 0.f);
        if (m0 + arow < M) av = *(const float4*)&A[(m0 + arow) * K + k0 + akq];
        float4 bv = *(const float4*)&Bm[(k0 + bkk) * N + n0 + bcol];
        __syncthreads();
        As[akq + 0][arow] = av.x; As[akq + 1][arow] = av.y;
        As[akq + 2][arow] = av.z; As[akq + 3][arow] = av.w;
        *(float4*)&Bs[bkk][bcol] = bv;
        __syncthreads();
        #pragma unroll
        for (int kk = 0; kk < 8; kk++) {
            float4 a0 = *(const float4*)&As[kk][tr * 8];
            float4 a1 = *(const float4*)&As[kk][tr * 8 + 4];
            float4 b0 = *(const float4*)&Bs[kk][tc * 8];
            float4 b1 = *(const float4*)&Bs[kk][tc * 8 + 4];
            float a[8] = {a0.x, a0.y, a0.z, a0.w, a1.x, a1.y, a1.z, a1.w};
            float b[8] = {b0.x, b0.y, b0.z, b0.w, b1.x, b1.y, b1.z, b1.w};
            #pragma unroll
            for (int i = 0; i < 8; i++)
                #pragma unroll
                for (int j = 0; j < 8; j++) acc[i][j] += a[i] * b[j];
        }
    }

    #pragma unroll
    for (int i = 0; i < 8; i++) {
        int gm = m0 + tr * 8 + i;
        if (gm >= M) continue;
        #pragma unroll
        for (int j = 0; j < 8; j++) {
            int gn = n0 + tc * 8 + j;
            float v = acc[i][j];
            if (bias) v += bias[gn];
            C[gm * N + gn] = v;
        }
    }
}

// ---------------- fused block-sparse attention (flash-style, 64x64 tiles) ----------------
// logits[i,j] = qc_i . k_j + qr_i . relk[j-i+N-1]   (relative-shift identity)
// mask(i,j)  = (| i/128 - j/128 | <= 1) || i<4 || j<4
#define LDS 65
#define SM_QC 0
#define SM_QR 4160
#define SM_K  8320
#define SM_V  12480
#define SM_RB 16640     // 127*65; P tile aliases this region
#define ATTN_SMEM_FLOATS (16640 + 127 * 65)

__global__ __launch_bounds__(256) void attn_kernel()
{
    extern __shared__ float sm[];
    float* Qcs = sm + SM_QC;
    float* Qrs = sm + SM_QR;
    float* Ks  = sm + SM_K;
    float* Vs  = sm + SM_V;
    float* RBs = sm + SM_RB;
    float* Ps  = sm + SM_RB;   // alias: rel-band dead by the time P is written

    const int qt = blockIdx.x;      // 0..23 query tiles of 64
    const int bh = blockIdx.y;      // 0..15
    const int b  = bh >> 3, h = bh & 7;
    const int i0 = qt * 64;
    const int tid = threadIdx.x;
    const int ty = tid >> 4, tx = tid & 15;
    const int r0 = ty * 4, c0 = tx * 4;

    // load query tiles
    const float* qcg = g_qc + (bh * NSEQ + i0) * DK;
    const float* qrg = g_qr + (bh * NSEQ + i0) * DK;
    for (int idx = tid; idx < 64 * 64; idx += 256) {
        int r = idx >> 6, d = idx & 63;
        Qcs[r * LDS + d] = qcg[r * 64 + d];
        Qrs[r * LDS + d] = qrg[r * 64 + d];
    }

    float m_i[4], l_i[4], O[4][4];
    #pragma unroll
    for (int rr = 0; rr < 4; rr++) {
        m_i[rr] = -1e30f; l_i[rr] = 0.f;
        #pragma unroll
        for (int cc = 0; cc < 4; cc++) O[rr][cc] = 0.f;
    }

    // build key-tile list (block-sparse + global)
    int kts[24]; int nkt = 0;
    const int bi = qt >> 1;
    if (qt == 0) {
        for (int t = 0; t < 24; t++) kts[nkt++] = t;   // global rows 0-3 see everything
    } else {
        int lo = (bi > 0 ? bi - 1 : 0) * 2;
        int hi = (bi < 11 ? bi + 1 : 11) * 2 + 1;
        if (lo > 0) kts[nkt++] = 0;                    // global columns 0-3
        for (int t = lo; t <= hi; t++) kts[nkt++] = t;
    }

    const float* kg = g_k + bh * NSEQ * DK;
    const float* vg = g_v + bh * NSEQ * DK;

    int rbrow[4][4];
    #pragma unroll
    for (int rr = 0; rr < 4; rr++)
        #pragma unroll
        for (int cc = 0; cc < 4; cc++)
            rbrow[rr][cc] = (c0 + cc - r0 - rr + 63) * LDS;

    for (int it = 0; it < nkt; it++) {
        const int j0 = kts[it] * 64;
        __syncthreads();   // previous iteration's P/V reads done before overwrite
        for (int idx = tid; idx < 64 * 64; idx += 256) {
            int r = idx >> 6, d = idx & 63;
            Ks[r * LDS + d] = kg[(j0 + r) * 64 + d];
            Vs[r * LDS + d] = vg[(j0 + r) * 64 + d];
        }
        const int gbase = (j0 - i0) + 1472;   // relk row for band offset 0  (= j0-i0-63+1535)
        for (int idx = tid; idx < 127 * 64; idx += 256) {
            int r = idx >> 6, d = idx & 63;
            RBs[r * LDS + d] = g_relk[(gbase + r) * HD + h * DK + d];
        }
        __syncthreads();

        // S = Qc.K^T + Qr.RelBand
        float S[4][4];
        #pragma unroll
        for (int rr = 0; rr < 4; rr++)
            #pragma unroll
            for (int cc = 0; cc < 4; cc++) S[rr][cc] = 0.f;

        for (int d = 0; d < 64; d++) {
            float qc4[4], qr4[4], k4[4];
            #pragma unroll
            for (int rr = 0; rr < 4; rr++) {
                qc4[rr] = Qcs[(r0 + rr) * LDS + d];
                qr4[rr] = Qrs[(r0 + rr) * LDS + d];
            }
            #pragma unroll
            for (int cc = 0; cc < 4; cc++) k4[cc] = Ks[(c0 + cc) * LDS + d];
            #pragma unroll
            for (int rr = 0; rr < 4; rr++)
                #pragma unroll
                for (int cc = 0; cc < 4; cc++)
                    S[rr][cc] += qc4[rr] * k4[cc] + qr4[rr] * RBs[rbrow[rr][cc] + d];
        }

        // mask
        #pragma unroll
        for (int rr = 0; rr < 4; rr++) {
            int ig = i0 + r0 + rr;
            int bqi = ig >> 7;
            #pragma unroll
            for (int cc = 0; cc < 4; cc++) {
                int jg = j0 + c0 + cc;
                int dlt = bqi - (jg >> 7); if (dlt < 0) dlt = -dlt;
                bool ok = (dlt <= 1) || (ig < 4) || (jg < 4);
                if (!ok) S[rr][cc] = -1e30f;
            }
        }

        // online softmax (row reduction across the 16 tx lanes of the warp)
        float mnew[4], psum[4];
        #pragma unroll
        for (int rr = 0; rr < 4; rr++) {
            float mx = S[rr][0];
            #pragma unroll
            for (int cc = 1; cc < 4; cc++) mx = fmaxf(mx, S[rr][cc]);
            #pragma unroll
            for (int off = 8; off >= 1; off >>= 1)
                mx = fmaxf(mx, __shfl_xor_sync(0xffffffffu, mx, off));
            mnew[rr] = fmaxf(m_i[rr], mx);
            float s = 0.f;
            #pragma unroll
            for (int cc = 0; cc < 4; cc++) {
                float p = __expf(S[rr][cc] - mnew[rr]);
                S[rr][cc] = p; s += p;
            }
            #pragma unroll
            for (int off = 8; off >= 1; off >>= 1)
                s += __shfl_xor_sync(0xffffffffu, s, off);
            psum[rr] = s;
        }

        __syncthreads();   // everyone done reading RBs before P overwrites it
        #pragma unroll
        for (int rr = 0; rr < 4; rr++) {
            float corr = __expf(m_i[rr] - mnew[rr]);
            l_i[rr] = l_i[rr] * corr + psum[rr];
            m_i[rr] = mnew[rr];
            #pragma unroll
            for (int cc = 0; cc < 4; cc++) {
                O[rr][cc] *= corr;
                Ps[(r0 + rr) * LDS + c0 + cc] = S[rr][cc];
            }
        }
        __syncthreads();

        // O += P @ V
        for (int j = 0; j < 64; j++) {
            float p4[4], v4[4];
            #pragma unroll
            for (int rr = 0; rr < 4; rr++) p4[rr] = Ps[(r0 + rr) * LDS + j];
            #pragma unroll
            for (int cc = 0; cc < 4; cc++) v4[cc] = Vs[j * LDS + c0 + cc];
            #pragma unroll
            for (int rr = 0; rr < 4; rr++)
                #pragma unroll
                for (int cc = 0; cc < 4; cc++) O[rr][cc] += p4[rr] * v4[cc];
        }
    }

    // normalize + write [b*n][h*64+d]
    #pragma unroll
    for (int rr = 0; rr < 4; rr++) {
        float inv = 1.f / l_i[rr];
        int ig = i0 + r0 + rr;
        #pragma unroll
        for (int cc = 0; cc < 4; cc++)
            g_ao[(b * NSEQ + ig) * HD + h * DK + c0 + cc] = O[rr][cc] * inv;
    }
}

// ---------------- launch ----------------
extern "C" void kernel_launch(void* const* d_in, const int* in_sizes, int n_in,
                              void* d_out, int out_size)
{
    const float* x    = (const float*)d_in[0];
    const float* Wq   = (const float*)d_in[1];
    const float* Wk   = (const float*)d_in[2];
    const float* Wv   = (const float*)d_in[3];
    const float* Wrel = (const float*)d_in[4];
    const float* rcb  = (const float*)d_in[5];
    const float* rpb  = (const float*)d_in[6];
    const float* Wo   = (const float*)d_in[7];
    const float* bo   = (const float*)d_in[8];
    const float* pe   = (const float*)d_in[9];
    float* out = (float*)d_out;

    void *relk_p = nullptr, *ao_p = nullptr;
    cudaGetSymbolAddress(&relk_p, g_relk);
    cudaGetSymbolAddress(&ao_p, g_ao);

    const int attn_smem = ATTN_SMEM_FLOATS * (int)sizeof(float);   // ~99.6 KB
    cudaFuncSetAttribute(attn_kernel, cudaFuncAttributeMaxDynamicSharedMemorySize, attn_smem);

    // 1. QKV projections (fused 3-way)
    qkv_gemm<<<dim3(4, 24, 3), 256>>>(x, Wq, Wk, Wv, rcb, rpb);

    // 2. rel_k = pos_embed @ Wrel   [3071, 512]
    sgemm_bias<<<dim3(4, 24), 256>>>(pe, Wrel, (float*)relk_p, NPOS, HD, NRPFK, nullptr);

    // 3. fused block-sparse attention with relative-shift term
    attn_kernel<<<dim3(24, 16), 256, attn_smem>>>();

    // 4. output projection + bias
    sgemm_bias<<<dim3(12, 24), 256>>>((const float*)ao_p, Wo, out, BN, DIMX, HD, bo);
}